// round 2
// baseline (speedup 1.0000x reference)
#include <cuda_runtime.h>
#include <math.h>

#define L_ 12
#define B_ 4
#define D_ 128
#define NMAX 30080
#define NCELL 289

#define SEL_SMEM ((128*192 + 128*128 + 64*128)*4)
#define SAMP_SMEM ((4*48*128 + 48*128)*4)

// ---------------- scratch ----------------
__device__ float g_pe[(size_t)NMAX * 192];
__device__ float g_feat[L_*B_*256*D_];   // [l,b,p,d], d contiguous
__device__ float g_gb[L_*B_*D_];
__device__ float g_selLayer[NMAX*L_];
__device__ float2 g_samp[NMAX];
__device__ float g_scale[NMAX];
__device__ int   g_cell[NMAX];
__device__ int   g_cnt[NCELL];
__device__ int   g_start[NCELL];
__device__ int   g_cur[NCELL];
__device__ int   g_bin[NMAX];
__device__ float g_acc[2];

__device__ __forceinline__ float gelu_exact(float x) {
    return 0.5f * x * (1.0f + erff(x * 0.70710678118654752440f));
}

__global__ void zero_kernel() {
    int t = threadIdx.x;
    if (t < NCELL) { g_cnt[t] = 0; g_cur[t] = 0; }
    if (t < 2) g_acc[t] = 0.f;
}

// ---------------- positional encoding ----------------
__global__ void pe_kernel(const float* __restrict__ coords, int N) {
    int idx = blockIdx.x * 256 + threadIdx.x;
    if (idx >= N * 96) return;
    int n = idx / 96, r = idx - n * 96;
    int c = r >> 5, f = r & 31;
    float fr = 3.14159265358979323846f * exp2f((float)f * (8.0f / 31.0f));
    float s, cv;
    sincosf(coords[n*3 + c] * fr, &s, &cv);
    g_pe[(size_t)n*192 + c*64 + f] = s;
    g_pe[(size_t)n*192 + c*64 + 32 + f] = cv;
}

// ---------------- tiled fp32 GEMM piece: out[128x128] = act(in[128xK] @ W[Kx128] + b) ----------------
__device__ __forceinline__ void mlp_gemm(
    const float* __restrict__ Wg, const float* __restrict__ bias,
    const float* inS, int K, float* outS, float* wS, int t, int act)
{
    const int mt = t >> 4, nt = t & 15;
    const int m0 = mt << 3, n0 = nt << 3;
    float acc[8][8];
    float bv[8];
    #pragma unroll
    for (int j = 0; j < 8; j++) bv[j] = bias[n0 + j];
    #pragma unroll
    for (int i = 0; i < 8; i++)
        #pragma unroll
        for (int j = 0; j < 8; j++) acc[i][j] = bv[j];

    for (int kb = 0; kb < K; kb += 64) {
        __syncthreads();
        for (int v = t; v < 64*32; v += 256)
            ((float4*)wS)[v] = ((const float4*)Wg)[(size_t)kb*32 + v];
        __syncthreads();
        #pragma unroll 2
        for (int k = 0; k < 64; k++) {
            float a[8];
            #pragma unroll
            for (int i = 0; i < 8; i++) a[i] = inS[(m0 + i)*K + kb + k];
            float4 q0 = *(const float4*)&wS[k*128 + n0];
            float4 q1 = *(const float4*)&wS[k*128 + n0 + 4];
            float bb[8] = {q0.x, q0.y, q0.z, q0.w, q1.x, q1.y, q1.z, q1.w};
            #pragma unroll
            for (int i = 0; i < 8; i++)
                #pragma unroll
                for (int j = 0; j < 8; j++) acc[i][j] = fmaf(a[i], bb[j], acc[i][j]);
        }
    }
    __syncthreads();
    #pragma unroll
    for (int i = 0; i < 8; i++) {
        float o[8];
        #pragma unroll
        for (int j = 0; j < 8; j++) o[j] = act ? gelu_exact(acc[i][j]) : acc[i][j];
        *(float4*)&outS[(m0 + i)*128 + n0]     = make_float4(o[0], o[1], o[2], o[3]);
        *(float4*)&outS[(m0 + i)*128 + n0 + 4] = make_float4(o[4], o[5], o[6], o[7]);
    }
}

// ---------------- selector: 3 heads, 128 points per block ----------------
__global__ void __launch_bounds__(256) selector_kernel(
    const float* __restrict__ W1, const float* __restrict__ b1,
    const float* __restrict__ W2, const float* __restrict__ b2,
    const float* __restrict__ W3s, const float* __restrict__ W3l,
    const float* __restrict__ W3c, int N)
{
    extern __shared__ float sm[];
    float* bufA = sm;                   // 128*192 (pe, then h2)
    float* bufB = sm + 128*192;         // 128*128 (h1)
    float* wS   = bufB + 128*128;       // 64*128
    const int t = threadIdx.x;
    const int base = blockIdx.x * 128;

    for (int head = 0; head < 3; head++) {
        __syncthreads();
        for (int v = t; v < 128*48; v += 256)
            ((float4*)bufA)[v] = ((const float4*)(g_pe + (size_t)base*192))[v];
        __syncthreads();
        mlp_gemm(W1 + (size_t)head*192*128, b1 + head*128, bufA, 192, bufB, wS, t, 1);
        __syncthreads();
        mlp_gemm(W2 + (size_t)head*128*128, b2 + head*128, bufB, 128, bufA, wS, t, 1);
        __syncthreads();

        float redval = 0.f;
        if (t < 128) {
            int n = base + t;
            if (n < N) {
                const float* h = &bufA[t*128];
                if (head == 0) {
                    float a0 = 0.f, a1 = 0.f;
                    for (int k = 0; k < 128; k++) {
                        float hv = h[k];
                        a0 = fmaf(hv, W3s[2*k], a0);
                        a1 = fmaf(hv, W3s[2*k + 1], a1);
                    }
                    float x = (tanhf(a0) + 1.f) * 8.f - 0.5f;
                    float y = (tanhf(a1) + 1.f) * 8.f - 0.5f;
                    float x0 = floorf(x), y0 = floorf(y);
                    g_samp[n] = make_float2(x - x0, y - y0);
                    int cx = min(max((int)x0 + 1, 0), 16);
                    int cy = min(max((int)y0 + 1, 0), 16);
                    int cell = cy * 17 + cx;
                    g_cell[n] = cell;
                    atomicAdd(&g_cnt[cell], 1);
                } else if (head == 1) {
                    float lg[12];
                    #pragma unroll
                    for (int o = 0; o < 12; o++) lg[o] = 0.f;
                    for (int k = 0; k < 128; k++) {
                        float hv = h[k];
                        #pragma unroll
                        for (int o = 0; o < 12; o++) lg[o] = fmaf(hv, W3l[k*12 + o], lg[o]);
                    }
                    float m = lg[0];
                    #pragma unroll
                    for (int o = 1; o < 12; o++) m = fmaxf(m, lg[o]);
                    float s = 0.f;
                    #pragma unroll
                    for (int o = 0; o < 12; o++) { lg[o] = expf(lg[o] - m); s += lg[o]; }
                    float inv = 1.f / s;
                    float ent = 0.f;
                    #pragma unroll
                    for (int o = 0; o < 12; o++) {
                        float pp = lg[o] * inv;
                        g_selLayer[n*12 + o] = pp;
                        ent += pp * logf(pp + 1e-8f);
                    }
                    redval = ent;
                } else {
                    float a0 = 0.f;
                    for (int k = 0; k < 128; k++) a0 = fmaf(h[k], W3c[k], a0);
                    float sg = 1.f / (1.f + expf(-a0));
                    g_scale[n] = sg;
                    float dd = sg - 0.5f;
                    redval = dd * dd;
                }
            }
        }
        __syncthreads();
        wS[t] = redval;
        __syncthreads();
        for (int s = 128; s > 0; s >>= 1) {
            if (t < s) wS[t] += wS[t + s];
            __syncthreads();
        }
        if (t == 0 && head == 1) atomicAdd(&g_acc[0], wS[0]);
        if (t == 0 && head == 2) atomicAdd(&g_acc[1], wS[0]);
    }
}

// ---------------- bin scan / fill ----------------
__global__ void scan_kernel() {
    __shared__ int sc[512];
    int t = threadIdx.x;
    int v = (t < NCELL) ? g_cnt[t] : 0;
    sc[t] = v;
    __syncthreads();
    for (int off = 1; off < 512; off <<= 1) {
        int add = (t >= off) ? sc[t - off] : 0;
        __syncthreads();
        sc[t] += add;
        __syncthreads();
    }
    if (t < NCELL) g_start[t] = sc[t] - v;
}

__global__ void fill_kernel(int N) {
    int n = blockIdx.x * 256 + threadIdx.x;
    if (n < N) {
        int c = g_cell[n];
        int s = atomicAdd(&g_cur[c], 1);
        g_bin[g_start[c] + s] = n;
    }
}

// ---------------- gb[l,b,d] = sum_c global_tokens[l,b,c]*glob_w[l,d,c] ----------------
__global__ void gb_kernel(const float* __restrict__ gt, const float* __restrict__ gw) {
    int gwid = blockIdx.x * 8 + (threadIdx.x >> 5);
    int lane = threadIdx.x & 31;
    if (gwid >= L_ * D_) return;
    int l = gwid >> 7, d = gwid & 127;
    const float* wrow = gw + ((size_t)l*128 + d)*768;
    #pragma unroll
    for (int b = 0; b < 4; b++) {
        const float* trow = gt + ((size_t)l*4 + b)*768;
        float acc = 0.f;
        for (int c = lane; c < 768; c += 32) acc = fmaf(trow[c], wrow[c], acc);
        #pragma unroll
        for (int o = 16; o > 0; o >>= 1) acc += __shfl_xor_sync(0xffffffffu, acc, o);
        if (lane == 0) g_gb[((size_t)l*4 + b)*128 + d] = acc;
    }
}

// ---------------- 1x1 conv: feat[l,b,p,d] = sum_c X[l,b,c,p]*W[l,d,c] ----------------
__global__ void __launch_bounds__(256) conv_kernel(
    const float* __restrict__ X, const float* __restrict__ W)
{
    __shared__ float xS[32*64];
    __shared__ float wS[32*128];
    int bx = blockIdx.x;
    int l = bx >> 4, r = bx & 15, b = r >> 2, pq = r & 3;
    int t = threadIdx.x;
    int tp = t >> 4, td = t & 15;
    const float* Xbase = X + ((size_t)(l*4 + b)*768)*256 + pq*64;
    const float* Wbase = W + (size_t)l*128*768;
    float acc[4][8];
    #pragma unroll
    for (int i = 0; i < 4; i++)
        #pragma unroll
        for (int j = 0; j < 8; j++) acc[i][j] = 0.f;

    for (int cb = 0; cb < 768; cb += 32) {
        __syncthreads();
        for (int v = t; v < 512; v += 256) {
            int k = v >> 4, i4 = v & 15;
            ((float4*)xS)[k*16 + i4] = *(const float4*)(Xbase + (size_t)(cb + k)*256 + i4*4);
        }
        for (int v = t; v < 1024; v += 256) {
            int d = v & 127, c4 = v >> 7;
            float4 wv = *(const float4*)(Wbase + (size_t)d*768 + cb + c4*4);
            wS[(c4*4 + 0)*128 + d] = wv.x;
            wS[(c4*4 + 1)*128 + d] = wv.y;
            wS[(c4*4 + 2)*128 + d] = wv.z;
            wS[(c4*4 + 3)*128 + d] = wv.w;
        }
        __syncthreads();
        #pragma unroll 4
        for (int k = 0; k < 32; k++) {
            float4 a = *(const float4*)&xS[k*64 + tp*4];
            float av[4] = {a.x, a.y, a.z, a.w};
            float4 q0 = *(const float4*)&wS[k*128 + td*8];
            float4 q1 = *(const float4*)&wS[k*128 + td*8 + 4];
            float bb[8] = {q0.x, q0.y, q0.z, q0.w, q1.x, q1.y, q1.z, q1.w};
            #pragma unroll
            for (int i = 0; i < 4; i++)
                #pragma unroll
                for (int j = 0; j < 8; j++) acc[i][j] = fmaf(av[i], bb[j], acc[i][j]);
        }
    }
    float* out = g_feat + (((size_t)(l*4 + b))*256 + pq*64 + tp*4)*128 + td*8;
    #pragma unroll
    for (int i = 0; i < 4; i++) {
        *(float4*)(out + (size_t)i*128)     = make_float4(acc[i][0], acc[i][1], acc[i][2], acc[i][3]);
        *(float4*)(out + (size_t)i*128 + 4) = make_float4(acc[i][4], acc[i][5], acc[i][6], acc[i][7]);
    }
}

// ---------------- fused sample + output ----------------
__global__ void __launch_bounds__(256) sample_kernel(
    const float* __restrict__ ow, const float* __restrict__ obias,
    float* __restrict__ y, int N)
{
    extern __shared__ float sh[];
    float* featS = sh;                 // [4][48][128]
    float* gbS = sh + 4*48*128;        // [48][128]
    const int bx = blockIdx.x;
    const int count = g_cnt[bx];
    const int start0 = (int)blockIdx.y * 64;
    if (start0 >= count) return;
    const int end = min(start0 + 64, count);
    const int t = threadIdx.x;
    const int cx = bx % 17, cy = bx / 17;
    const int px0 = cx - 1, py0 = cy - 1;

    for (int v = t; v < 1536; v += 256)
        ((float4*)gbS)[v] = ((const float4*)g_gb)[v];
    for (int v = t; v < 6144; v += 256) {
        int cr = v / 1536, rem = v - cr*1536;
        int lb = rem >> 5, i = rem & 31;
        int px = px0 + (cr & 1), py = py0 + (cr >> 1);
        float4 val = make_float4(0.f, 0.f, 0.f, 0.f);
        if (px >= 0 && px < 16 && py >= 0 && py < 16)
            val = ((const float4*)(g_feat + ((size_t)lb*256 + py*16 + px)*128))[i];
        ((float4*)featS)[v] = val;
    }
    __syncthreads();

    const int wid = t >> 5, lane = t & 31;
    const int sbase = g_start[bx];
    const float4* fS4 = (const float4*)featS;
    const float4* gbS4 = (const float4*)gbS;

    for (int i0 = start0 + wid*2; i0 < end; i0 += 16) {
        int n0 = g_bin[sbase + i0];
        int has1 = (i0 + 1 < end);
        int n1 = has1 ? g_bin[sbase + i0 + 1] : n0;

        float2 s0 = g_samp[n0], s1 = g_samp[n1];
        float sc0 = g_scale[n0], sc1 = g_scale[n1];
        float w0[4] = {(1.f - s0.x)*(1.f - s0.y), s0.x*(1.f - s0.y),
                       (1.f - s0.x)*s0.y,         s0.x*s0.y};
        float w1[4] = {(1.f - s1.x)*(1.f - s1.y), s1.x*(1.f - s1.y),
                       (1.f - s1.x)*s1.y,         s1.x*s1.y};
        float4 ow0 = *(const float4*)&ow[(size_t)n0*128 + lane*4];
        float4 ow1 = *(const float4*)&ow[(size_t)n1*128 + lane*4];
        float acc0[4] = {0.f, 0.f, 0.f, 0.f};
        float acc1[4] = {0.f, 0.f, 0.f, 0.f};
        const float* pl0 = g_selLayer + n0*12;
        const float* pl1 = g_selLayer + n1*12;

        for (int l = 0; l < 12; l++) {
            float p0 = pl0[l], p1 = pl1[l];
            float a0 = p0*(1.f - sc0), a1 = p1*(1.f - sc1);
            float c00 = a0*w0[0], c01 = a0*w0[1], c02 = a0*w0[2], c03 = a0*w0[3];
            float c10 = a1*w1[0], c11 = a1*w1[1], c12 = a1*w1[2], c13 = a1*w1[3];
            float g0 = p0*sc0, g1 = p1*sc1;
            #pragma unroll
            for (int b = 0; b < 4; b++) {
                int lb = l*4 + b;
                float4 f0 = fS4[(0*48 + lb)*32 + lane];
                float4 f1 = fS4[(1*48 + lb)*32 + lane];
                float4 f2 = fS4[(2*48 + lb)*32 + lane];
                float4 f3 = fS4[(3*48 + lb)*32 + lane];
                float4 gv = gbS4[lb*32 + lane];
                float vx = fmaf(c00, f0.x, fmaf(c01, f1.x, fmaf(c02, f2.x, fmaf(c03, f3.x, g0*gv.x))));
                float vy = fmaf(c00, f0.y, fmaf(c01, f1.y, fmaf(c02, f2.y, fmaf(c03, f3.y, g0*gv.y))));
                float vz = fmaf(c00, f0.z, fmaf(c01, f1.z, fmaf(c02, f2.z, fmaf(c03, f3.z, g0*gv.z))));
                float vw = fmaf(c00, f0.w, fmaf(c01, f1.w, fmaf(c02, f2.w, fmaf(c03, f3.w, g0*gv.w))));
                acc0[b] += fmaf(vx, ow0.x, fmaf(vy, ow0.y, fmaf(vz, ow0.z, vw*ow0.w)));
                float ux = fmaf(c10, f0.x, fmaf(c11, f1.x, fmaf(c12, f2.x, fmaf(c13, f3.x, g1*gv.x))));
                float uy = fmaf(c10, f0.y, fmaf(c11, f1.y, fmaf(c12, f2.y, fmaf(c13, f3.y, g1*gv.y))));
                float uz = fmaf(c10, f0.z, fmaf(c11, f1.z, fmaf(c12, f2.z, fmaf(c13, f3.z, g1*gv.z))));
                float uw = fmaf(c10, f0.w, fmaf(c11, f1.w, fmaf(c12, f2.w, fmaf(c13, f3.w, g1*gv.w))));
                acc1[b] += fmaf(ux, ow1.x, fmaf(uy, ow1.y, fmaf(uz, ow1.z, uw*ow1.w)));
            }
        }
        #pragma unroll
        for (int b = 0; b < 4; b++) {
            #pragma unroll
            for (int o = 16; o > 0; o >>= 1) {
                acc0[b] += __shfl_xor_sync(0xffffffffu, acc0[b], o);
                acc1[b] += __shfl_xor_sync(0xffffffffu, acc1[b], o);
            }
        }
        if (lane == 0) {
            float bi0 = obias[n0];
            #pragma unroll
            for (int b = 0; b < 4; b++) y[(size_t)b*N + n0] = acc0[b]*0.0078125f + bi0;
            if (has1) {
                float bi1 = obias[n1];
                #pragma unroll
                for (int b = 0; b < 4; b++) y[(size_t)b*N + n1] = acc1[b]*0.0078125f + bi1;
            }
        }
    }
}

__global__ void finalize_kernel(float* __restrict__ out, int N, int out_size) {
    if (out_size > 4*N)
        out[4*N] = g_acc[0] / ((float)N * logf(12.0f)) + g_acc[1] / (float)N;
}

extern "C" void kernel_launch(void* const* d_in, const int* in_sizes, int n_in,
                              void* d_out, int out_size) {
    const float* local_tokens = (const float*)d_in[0];
    const float* global_tokens = (const float*)d_in[1];
    const float* coords = (const float*)d_in[2];
    const float* conv_w = (const float*)d_in[3];
    const float* glob_w = (const float*)d_in[4];
    const float* W1 = (const float*)d_in[5];
    const float* b1 = (const float*)d_in[6];
    const float* W2 = (const float*)d_in[7];
    const float* b2 = (const float*)d_in[8];
    const float* W3s = (const float*)d_in[9];
    const float* W3l = (const float*)d_in[10];
    const float* W3c = (const float*)d_in[11];
    const float* ow = (const float*)d_in[12];
    const float* obias = (const float*)d_in[13];
    float* out = (float*)d_out;
    int N = in_sizes[2] / 3;

    cudaFuncSetAttribute(selector_kernel, cudaFuncAttributeMaxDynamicSharedMemorySize, SEL_SMEM);
    cudaFuncSetAttribute(sample_kernel, cudaFuncAttributeMaxDynamicSharedMemorySize, SAMP_SMEM);

    zero_kernel<<<1, 512>>>();
    pe_kernel<<<(N*96 + 255)/256, 256>>>(coords, N);
    gb_kernel<<<192, 256>>>(global_tokens, glob_w);
    conv_kernel<<<192, 256>>>(local_tokens, conv_w);
    selector_kernel<<<(N + 127)/128, 256, SEL_SMEM>>>(W1, b1, W2, b2, W3s, W3l, W3c, N);
    scan_kernel<<<1, 512>>>();
    fill_kernel<<<(N + 255)/256, 256>>>(N);
    sample_kernel<<<dim3(NCELL, (N + 63)/64), 256, SAMP_SMEM>>>(ow, obias, out, N);
    finalize_kernel<<<1, 1>>>(out, N, out_size);
}

// round 4
// speedup vs baseline: 1.6184x; 1.6184x over previous
#include <cuda_runtime.h>
#include <stdint.h>
#include <math.h>

#define L_ 12
#define B_ 4
#define D_ 128
#define NMAX 30080
#define NCELL 289

#define SEL_SMEM ((128*192 + 128*128 + 2*64*128)*4)
#define SAMP_SMEM ((4*48*128 + 48*128)*4)

// ---------------- scratch ----------------
__device__ float g_pe[(size_t)NMAX * 192];
__device__ float g_wT[L_*768*D_];        // conv_w transposed: [l][c][d]
__device__ float g_feat[L_*B_*256*D_];   // [l,b,p,d], d contiguous
__device__ float g_gb[L_*B_*D_];
__device__ float g_selLayer[NMAX*L_];
__device__ float2 g_samp[NMAX];
__device__ float g_scale[NMAX];
__device__ int   g_cell[NMAX];
__device__ int   g_cnt[NCELL];
__device__ int   g_start[NCELL];
__device__ int   g_cur[NCELL];
__device__ int   g_bin[NMAX];
__device__ float g_acc[2];

// ---------------- helpers ----------------
__device__ __forceinline__ float gelu_exact(float x) {
    return 0.5f * x * (1.0f + erff(x * 0.70710678118654752440f));
}
__device__ __forceinline__ void cpa16(uint32_t d, const void* s) {
    asm volatile("cp.async.ca.shared.global [%0], [%1], 16;" :: "r"(d), "l"(s));
}
__device__ __forceinline__ void cpcommit() {
    asm volatile("cp.async.commit_group;");
}
template<int NN> __device__ __forceinline__ void cpwait() {
    asm volatile("cp.async.wait_group %0;" :: "n"(NN));
}

__global__ void zero_kernel() {
    int t = threadIdx.x;
    if (t < NCELL) { g_cnt[t] = 0; g_cur[t] = 0; }
    if (t < 2) g_acc[t] = 0.f;
}

// ---------------- conv_w transpose: W[l][d][c] -> g_wT[l][c][d] ----------------
__global__ void __launch_bounds__(256) wt_kernel(const float* __restrict__ W) {
    __shared__ float tile[32][33];
    int l = blockIdx.z;
    int ct = blockIdx.x * 32, dt = blockIdx.y * 32;
    int tx = threadIdx.x & 31, ty = threadIdx.x >> 5;
    #pragma unroll
    for (int j = ty; j < 32; j += 8)
        tile[j][tx] = W[((size_t)l*128 + dt + j)*768 + ct + tx];
    __syncthreads();
    #pragma unroll
    for (int j = ty; j < 32; j += 8)
        g_wT[((size_t)l*768 + ct + j)*128 + dt + tx] = tile[tx][j];
}

// ---------------- positional encoding ----------------
__global__ void pe_kernel(const float* __restrict__ coords, int N) {
    int idx = blockIdx.x * 256 + threadIdx.x;
    if (idx >= N * 96) return;
    int n = idx / 96, r = idx - n * 96;
    int c = r >> 5, f = r & 31;
    float fr = 3.14159265358979323846f * exp2f((float)f * (8.0f / 31.0f));
    float s, cv;
    sincosf(coords[n*3 + c] * fr, &s, &cv);
    g_pe[(size_t)n*192 + c*64 + f] = s;
    g_pe[(size_t)n*192 + c*64 + 32 + f] = cv;
}

// ---------------- double-buffered GEMM piece: out[128x128] = gelu(in[128xK] @ W[Kx128] + b) ----------------
__device__ __forceinline__ void mlp_gemm(
    const float* __restrict__ Wg, const float* __restrict__ bias,
    const float* inS, int K, float* outS, float* wS2, int t, int act)
{
    const int m0 = (t >> 4) << 3, n0 = (t & 15) << 3;
    float acc[8][8];
    float bv[8];
    #pragma unroll
    for (int j = 0; j < 8; j++) bv[j] = bias[n0 + j];
    #pragma unroll
    for (int i = 0; i < 8; i++)
        #pragma unroll
        for (int j = 0; j < 8; j++) acc[i][j] = bv[j];

    uint32_t wAddr = (uint32_t)__cvta_generic_to_shared(wS2);
    for (int v = t; v < 2048; v += 256)
        cpa16(wAddr + v*16, (const float4*)Wg + v);
    cpcommit();

    int buf = 0;
    for (int kb = 0; kb < K; kb += 64) {
        if (kb + 64 < K) {
            const float4* src = (const float4*)(Wg + (size_t)(kb + 64)*128);
            uint32_t dA = wAddr + (buf ^ 1)*32768;
            for (int v = t; v < 2048; v += 256) cpa16(dA + v*16, src + v);
            cpcommit();
            cpwait<1>();
        } else {
            cpwait<0>();
        }
        __syncthreads();
        const float* wC = wS2 + buf*8192;
        #pragma unroll 2
        for (int k = 0; k < 64; k++) {
            float a[8];
            #pragma unroll
            for (int i = 0; i < 8; i++) a[i] = inS[(m0 + i)*K + kb + k];
            float4 q0 = *(const float4*)&wC[k*128 + n0];
            float4 q1 = *(const float4*)&wC[k*128 + n0 + 4];
            float bb[8] = {q0.x, q0.y, q0.z, q0.w, q1.x, q1.y, q1.z, q1.w};
            #pragma unroll
            for (int i = 0; i < 8; i++)
                #pragma unroll
                for (int j = 0; j < 8; j++) acc[i][j] = fmaf(a[i], bb[j], acc[i][j]);
        }
        __syncthreads();
        buf ^= 1;
    }
    #pragma unroll
    for (int i = 0; i < 8; i++) {
        float o[8];
        #pragma unroll
        for (int j = 0; j < 8; j++) o[j] = act ? gelu_exact(acc[i][j]) : acc[i][j];
        *(float4*)&outS[(m0 + i)*128 + n0]     = make_float4(o[0], o[1], o[2], o[3]);
        *(float4*)&outS[(m0 + i)*128 + n0 + 4] = make_float4(o[4], o[5], o[6], o[7]);
    }
}

// ---------------- selector: grid (ceil(N/128), 3 heads) ----------------
__global__ void __launch_bounds__(256) selector_kernel(
    const float* __restrict__ W1, const float* __restrict__ b1,
    const float* __restrict__ W2, const float* __restrict__ b2,
    const float* __restrict__ W3s, const float* __restrict__ W3l,
    const float* __restrict__ W3c, int N)
{
    extern __shared__ float sm[];
    float* bufA = sm;                   // 128*192 (pe, then h2 with stride 128)
    float* bufB = sm + 128*192;         // 128*128 (h1)
    float* wS   = bufB + 128*128;       // 2 * 64*128
    const int t = threadIdx.x;
    const int head = blockIdx.y;
    const int base = blockIdx.x * 128;

    // stage PE via cp.async
    {
        uint32_t dst = (uint32_t)__cvta_generic_to_shared(bufA);
        const float4* src = (const float4*)(g_pe + (size_t)base*192);
        for (int v = t; v < 6144; v += 256) cpa16(dst + v*16, src + v);
        cpcommit();
    }
    mlp_gemm(W1 + (size_t)head*192*128, b1 + head*128, bufA, 192, bufB, wS, t, 1);
    mlp_gemm(W2 + (size_t)head*128*128, b2 + head*128, bufB, 128, bufA, wS, t, 1);
    __syncthreads();

    float redval = 0.f;
    if (t < 128) {
        int n = base + t;
        if (n < N) {
            const float* h = &bufA[t*128];
            if (head == 0) {
                float a0 = 0.f, a1 = 0.f;
                for (int k = 0; k < 128; k++) {
                    float hv = h[k];
                    a0 = fmaf(hv, W3s[2*k], a0);
                    a1 = fmaf(hv, W3s[2*k + 1], a1);
                }
                float x = (tanhf(a0) + 1.f) * 8.f - 0.5f;
                float y = (tanhf(a1) + 1.f) * 8.f - 0.5f;
                float x0 = floorf(x), y0 = floorf(y);
                g_samp[n] = make_float2(x - x0, y - y0);
                int cx = min(max((int)x0 + 1, 0), 16);
                int cy = min(max((int)y0 + 1, 0), 16);
                int cell = cy * 17 + cx;
                g_cell[n] = cell;
                atomicAdd(&g_cnt[cell], 1);
            } else if (head == 1) {
                float lg[12];
                #pragma unroll
                for (int o = 0; o < 12; o++) lg[o] = 0.f;
                for (int k = 0; k < 128; k++) {
                    float hv = h[k];
                    #pragma unroll
                    for (int o = 0; o < 12; o++) lg[o] = fmaf(hv, W3l[k*12 + o], lg[o]);
                }
                float m = lg[0];
                #pragma unroll
                for (int o = 1; o < 12; o++) m = fmaxf(m, lg[o]);
                float s = 0.f;
                #pragma unroll
                for (int o = 0; o < 12; o++) { lg[o] = expf(lg[o] - m); s += lg[o]; }
                float inv = 1.f / s;
                float ent = 0.f;
                #pragma unroll
                for (int o = 0; o < 12; o++) {
                    float pp = lg[o] * inv;
                    g_selLayer[n*12 + o] = pp;
                    ent += pp * logf(pp + 1e-8f);
                }
                redval = ent;
            } else {
                float a0 = 0.f;
                for (int k = 0; k < 128; k++) a0 = fmaf(h[k], W3c[k], a0);
                float sg = 1.f / (1.f + expf(-a0));
                g_scale[n] = sg;
                float dd = sg - 0.5f;
                redval = dd * dd;
            }
        }
    }
    if (head == 0) return;
    __syncthreads();
    wS[t] = redval;
    __syncthreads();
    for (int s = 128; s > 0; s >>= 1) {
        if (t < s) wS[t] += wS[t + s];
        __syncthreads();
    }
    if (t == 0) atomicAdd(&g_acc[head - 1], wS[0]);
}

// ---------------- bin scan / fill ----------------
__global__ void scan_kernel() {
    __shared__ int sc[512];
    int t = threadIdx.x;
    int v = (t < NCELL) ? g_cnt[t] : 0;
    sc[t] = v;
    __syncthreads();
    for (int off = 1; off < 512; off <<= 1) {
        int add = (t >= off) ? sc[t - off] : 0;
        __syncthreads();
        sc[t] += add;
        __syncthreads();
    }
    if (t < NCELL) g_start[t] = sc[t] - v;
}

__global__ void fill_kernel(int N) {
    int n = blockIdx.x * 256 + threadIdx.x;
    if (n < N) {
        int c = g_cell[n];
        int s = atomicAdd(&g_cur[c], 1);
        g_bin[g_start[c] + s] = n;
    }
}

// ---------------- gb[l,b,d] ----------------
__global__ void gb_kernel(const float* __restrict__ gt, const float* __restrict__ gw) {
    int gwid = blockIdx.x * 8 + (threadIdx.x >> 5);
    int lane = threadIdx.x & 31;
    if (gwid >= L_ * D_) return;
    int l = gwid >> 7, d = gwid & 127;
    const float* wrow = gw + ((size_t)l*128 + d)*768;
    #pragma unroll
    for (int b = 0; b < 4; b++) {
        const float* trow = gt + ((size_t)l*4 + b)*768;
        float acc = 0.f;
        for (int c = lane; c < 768; c += 32) acc = fmaf(trow[c], wrow[c], acc);
        #pragma unroll
        for (int o = 16; o > 0; o >>= 1) acc += __shfl_xor_sync(0xffffffffu, acc, o);
        if (lane == 0) g_gb[((size_t)l*4 + b)*128 + d] = acc;
    }
}

// ---------------- 1x1 conv (double-buffered cp.async): grid 384 ----------------
__global__ void __launch_bounds__(256) conv_kernel(const float* __restrict__ X)
{
    __shared__ float xS[2][32*32];
    __shared__ float wS[2][32*128];
    int bx = blockIdx.x;
    int l = bx >> 5, r = bx & 31, b = r >> 3, pt = r & 7;
    int t = threadIdx.x, td = t & 31, tp = t >> 5;
    const float* Xb = X + ((size_t)(l*4 + b)*768)*256 + pt*32;
    const float* Wb = g_wT + (size_t)l*768*128;
    float acc[4][4];
    #pragma unroll
    for (int i = 0; i < 4; i++)
        #pragma unroll
        for (int j = 0; j < 4; j++) acc[i][j] = 0.f;

    uint32_t xA = (uint32_t)__cvta_generic_to_shared(&xS[0][0]);
    uint32_t wA = (uint32_t)__cvta_generic_to_shared(&wS[0][0]);
    int xk = t >> 3, xi = t & 7;

    // prefetch chunk 0
    cpa16(xA + t*16, Xb + (size_t)xk*256 + xi*4);
    #pragma unroll
    for (int j = 0; j < 4; j++) {
        int v = t + j*256;
        cpa16(wA + v*16, Wb + (size_t)(v >> 5)*128 + (v & 31)*4);
    }
    cpcommit();

    int buf = 0;
    for (int cb = 0; cb < 768; cb += 32) {
        if (cb + 32 < 768) {
            uint32_t xD = xA + (buf ^ 1)*4096;
            uint32_t wD = wA + (buf ^ 1)*16384;
            cpa16(xD + t*16, Xb + (size_t)(cb + 32 + xk)*256 + xi*4);
            #pragma unroll
            for (int j = 0; j < 4; j++) {
                int v = t + j*256;
                cpa16(wD + v*16, Wb + (size_t)(cb + 32 + (v >> 5))*128 + (v & 31)*4);
            }
            cpcommit();
            cpwait<1>();
        } else {
            cpwait<0>();
        }
        __syncthreads();
        const float* xC = &xS[buf][0];
        const float* wC = &wS[buf][0];
        #pragma unroll 4
        for (int k = 0; k < 32; k++) {
            float4 a = *(const float4*)&xC[k*32 + tp*4];
            float4 w = *(const float4*)&wC[k*128 + td*4];
            float av[4] = {a.x, a.y, a.z, a.w};
            float wv[4] = {w.x, w.y, w.z, w.w};
            #pragma unroll
            for (int i = 0; i < 4; i++)
                #pragma unroll
                for (int j = 0; j < 4; j++) acc[i][j] = fmaf(av[i], wv[j], acc[i][j]);
        }
        __syncthreads();
        buf ^= 1;
    }
    float* out = g_feat + ((size_t)((l*4 + b)*256 + pt*32 + tp*4))*128 + td*4;
    #pragma unroll
    for (int i = 0; i < 4; i++)
        *(float4*)(out + (size_t)i*128) = make_float4(acc[i][0], acc[i][1], acc[i][2], acc[i][3]);
}

// ---------------- fused sample + output: grid (289, 8) ----------------
__global__ void __launch_bounds__(256) sample_kernel(
    const float* __restrict__ ow, const float* __restrict__ obias,
    float* __restrict__ y, int N)
{
    extern __shared__ float sh[];
    float* featS = sh;                 // [4][48][128]
    float* gbS = sh + 4*48*128;        // [48][128]
    const int bx = blockIdx.x;
    const int count = g_cnt[bx];
    if ((int)blockIdx.y * 16 >= count) return;
    const int t = threadIdx.x;
    const int cx = bx % 17, cy = bx / 17;
    const int px0 = cx - 1, py0 = cy - 1;

    for (int v = t; v < 1536; v += 256)
        ((float4*)gbS)[v] = ((const float4*)g_gb)[v];
    for (int v = t; v < 6144; v += 256) {
        int cr = v / 1536, rem = v - cr*1536;
        int lb = rem >> 5, i = rem & 31;
        int px = px0 + (cr & 1), py = py0 + (cr >> 1);
        float4 val = make_float4(0.f, 0.f, 0.f, 0.f);
        if (px >= 0 && px < 16 && py >= 0 && py < 16)
            val = ((const float4*)(g_feat + ((size_t)lb*256 + py*16 + px)*128))[i];
        ((float4*)featS)[v] = val;
    }
    __syncthreads();

    const int wid = t >> 5, lane = t & 31;
    const int sbase = g_start[bx];
    const float4* fS4 = (const float4*)featS;
    const float4* gbS4 = (const float4*)gbS;

    for (int i0 = ((int)blockIdx.y*8 + wid)*2; i0 < count; i0 += 128) {
        int n0 = g_bin[sbase + i0];
        int has1 = (i0 + 1 < count);
        int n1 = has1 ? g_bin[sbase + i0 + 1] : n0;

        float2 s0 = g_samp[n0], s1 = g_samp[n1];
        float sc0 = g_scale[n0], sc1 = g_scale[n1];
        float w0[4] = {(1.f - s0.x)*(1.f - s0.y), s0.x*(1.f - s0.y),
                       (1.f - s0.x)*s0.y,         s0.x*s0.y};
        float w1[4] = {(1.f - s1.x)*(1.f - s1.y), s1.x*(1.f - s1.y),
                       (1.f - s1.x)*s1.y,         s1.x*s1.y};
        float4 ow0 = *(const float4*)&ow[(size_t)n0*128 + lane*4];
        float4 ow1 = *(const float4*)&ow[(size_t)n1*128 + lane*4];
        float acc0[4] = {0.f, 0.f, 0.f, 0.f};
        float acc1[4] = {0.f, 0.f, 0.f, 0.f};
        const float* pl0 = g_selLayer + n0*12;
        const float* pl1 = g_selLayer + n1*12;

        for (int l = 0; l < 12; l++) {
            float p0 = pl0[l], p1 = pl1[l];
            float a0 = p0*(1.f - sc0), a1 = p1*(1.f - sc1);
            float c00 = a0*w0[0], c01 = a0*w0[1], c02 = a0*w0[2], c03 = a0*w0[3];
            float c10 = a1*w1[0], c11 = a1*w1[1], c12 = a1*w1[2], c13 = a1*w1[3];
            float g0 = p0*sc0, g1 = p1*sc1;
            #pragma unroll
            for (int b = 0; b < 4; b++) {
                int lb = l*4 + b;
                float4 f0 = fS4[(0*48 + lb)*32 + lane];
                float4 f1 = fS4[(1*48 + lb)*32 + lane];
                float4 f2 = fS4[(2*48 + lb)*32 + lane];
                float4 f3 = fS4[(3*48 + lb)*32 + lane];
                float4 gv = gbS4[lb*32 + lane];
                float vx = fmaf(c00, f0.x, fmaf(c01, f1.x, fmaf(c02, f2.x, fmaf(c03, f3.x, g0*gv.x))));
                float vy = fmaf(c00, f0.y, fmaf(c01, f1.y, fmaf(c02, f2.y, fmaf(c03, f3.y, g0*gv.y))));
                float vz = fmaf(c00, f0.z, fmaf(c01, f1.z, fmaf(c02, f2.z, fmaf(c03, f3.z, g0*gv.z))));
                float vw = fmaf(c00, f0.w, fmaf(c01, f1.w, fmaf(c02, f2.w, fmaf(c03, f3.w, g0*gv.w))));
                acc0[b] += fmaf(vx, ow0.x, fmaf(vy, ow0.y, fmaf(vz, ow0.z, vw*ow0.w)));
                float ux = fmaf(c10, f0.x, fmaf(c11, f1.x, fmaf(c12, f2.x, fmaf(c13, f3.x, g1*gv.x))));
                float uy = fmaf(c10, f0.y, fmaf(c11, f1.y, fmaf(c12, f2.y, fmaf(c13, f3.y, g1*gv.y))));
                float uz = fmaf(c10, f0.z, fmaf(c11, f1.z, fmaf(c12, f2.z, fmaf(c13, f3.z, g1*gv.z))));
                float uw = fmaf(c10, f0.w, fmaf(c11, f1.w, fmaf(c12, f2.w, fmaf(c13, f3.w, g1*gv.w))));
                acc1[b] += fmaf(ux, ow1.x, fmaf(uy, ow1.y, fmaf(uz, ow1.z, uw*ow1.w)));
            }
        }
        #pragma unroll
        for (int b = 0; b < 4; b++) {
            #pragma unroll
            for (int o = 16; o > 0; o >>= 1) {
                acc0[b] += __shfl_xor_sync(0xffffffffu, acc0[b], o);
                acc1[b] += __shfl_xor_sync(0xffffffffu, acc1[b], o);
            }
        }
        if (lane == 0) {
            float bi0 = obias[n0];
            #pragma unroll
            for (int b = 0; b < 4; b++) y[(size_t)b*N + n0] = acc0[b]*0.0078125f + bi0;
            if (has1) {
                float bi1 = obias[n1];
                #pragma unroll
                for (int b = 0; b < 4; b++) y[(size_t)b*N + n1] = acc1[b]*0.0078125f + bi1;
            }
        }
    }
}

__global__ void finalize_kernel(float* __restrict__ out, int N, int out_size) {
    if (out_size > 4*N)
        out[4*N] = g_acc[0] / ((float)N * logf(12.0f)) + g_acc[1] / (float)N;
}

extern "C" void kernel_launch(void* const* d_in, const int* in_sizes, int n_in,
                              void* d_out, int out_size) {
    const float* local_tokens = (const float*)d_in[0];
    const float* global_tokens = (const float*)d_in[1];
    const float* coords = (const float*)d_in[2];
    const float* conv_w = (const float*)d_in[3];
    const float* glob_w = (const float*)d_in[4];
    const float* W1 = (const float*)d_in[5];
    const float* b1 = (const float*)d_in[6];
    const float* W2 = (const float*)d_in[7];
    const float* b2 = (const float*)d_in[8];
    const float* W3s = (const float*)d_in[9];
    const float* W3l = (const float*)d_in[10];
    const float* W3c = (const float*)d_in[11];
    const float* ow = (const float*)d_in[12];
    const float* obias = (const float*)d_in[13];
    float* out = (float*)d_out;
    int N = in_sizes[2] / 3;

    cudaFuncSetAttribute(selector_kernel, cudaFuncAttributeMaxDynamicSharedMemorySize, SEL_SMEM);
    cudaFuncSetAttribute(sample_kernel, cudaFuncAttributeMaxDynamicSharedMemorySize, SAMP_SMEM);

    zero_kernel<<<1, 512>>>();
    wt_kernel<<<dim3(24, 4, 12), 256>>>(conv_w);
    pe_kernel<<<(N*96 + 255)/256, 256>>>(coords, N);
    gb_kernel<<<192, 256>>>(global_tokens, glob_w);
    conv_kernel<<<384, 256>>>(local_tokens);
    selector_kernel<<<dim3((N + 127)/128, 3), 256, SEL_SMEM>>>(W1, b1, W2, b2, W3s, W3l, W3c, N);
    scan_kernel<<<1, 512>>>();
    fill_kernel<<<(N + 255)/256, 256>>>(N);
    sample_kernel<<<dim3(NCELL, 8), 256, SAMP_SMEM>>>(ow, obias, out, N);
    finalize_kernel<<<1, 1>>>(out, N, out_size);
}